// round 1
// baseline (speedup 1.0000x reference)
#include <cuda_runtime.h>
#include <math.h>

#define SEQ 2048
#define BATCH 2
#define DIN 768
#define NHEAD 8
#define HDIM 64
#define NEGV 1000000000000.0f

// Scratch: rotated start/end projections, layout [b][o][s][h] (K-major for A*B^T)
__device__ float g_SR[BATCH * NHEAD * SEQ * HDIM];
__device__ float g_ER[BATCH * NHEAD * SEQ * HDIM];

// ---------------------------------------------------------------------------
// Kernel 1: projection GEMM (M=4096, N=512, K=768) + bias + interleaved rotary
// blockIdx.z = 0 -> Ws/bs -> g_SR (scaled by 1/8), z = 1 -> We/be -> g_ER
// Tile: BM=64, BN=64, BK=16, 256 threads, 4x4 micro-tile.
// ---------------------------------------------------------------------------
__global__ __launch_bounds__(256) void proj_rope_kernel(
    const float* __restrict__ X,
    const float* __restrict__ Ws, const float* __restrict__ bs,
    const float* __restrict__ We, const float* __restrict__ be)
{
    const int which = blockIdx.z;
    const float* __restrict__ W = which ? We : Ws;
    const float* __restrict__ bias = which ? be : bs;
    float* __restrict__ dst = which ? g_ER : g_SR;
    const float scale = which ? 1.0f : 0.125f;  // 1/sqrt(64) folded into start

    __shared__ float As[16][68];   // [k][m]
    __shared__ float Bs[16][64];   // [k][n]
    __shared__ float inv_sh[32];

    const int tid = threadIdx.x;
    const int tx = tid & 15;
    const int ty = tid >> 4;

    if (tid < 32) {
        // 10000^(-i/32), double precision table
        inv_sh[tid] = (float)exp(-(double)tid * 9.210340371976184 / 32.0);
    }

    const int row0 = blockIdx.y * 64;   // M tile base (b*2048+s)
    const int col0 = blockIdx.x * 64;   // N tile base (o*64+h)

    // load indices
    const int aRow = tid >> 2;          // 0..63
    const int aK   = (tid & 3) * 4;     // 0,4,8,12
    const int bK   = tid >> 4;          // 0..15
    const int bN   = (tid & 15) * 4;    // 0..60

    float acc[4][4];
#pragma unroll
    for (int i = 0; i < 4; i++)
#pragma unroll
        for (int j = 0; j < 4; j++) acc[i][j] = 0.0f;

    for (int k0 = 0; k0 < DIN; k0 += 16) {
        __syncthreads();
        // A tile: X[row0+aRow][k0+aK .. +3] -> As[k][m] (transposed)
        float4 av = *(const float4*)&X[(size_t)(row0 + aRow) * DIN + k0 + aK];
        As[aK + 0][aRow] = av.x;
        As[aK + 1][aRow] = av.y;
        As[aK + 2][aRow] = av.z;
        As[aK + 3][aRow] = av.w;
        // B tile: W[k0+bK][col0+bN .. +3]
        *(float4*)&Bs[bK][bN] = *(const float4*)&W[(size_t)(k0 + bK) * (NHEAD * HDIM) + col0 + bN];
        __syncthreads();

#pragma unroll
        for (int k = 0; k < 16; k++) {
            float4 a = *(const float4*)&As[k][ty * 4];
            float4 b = *(const float4*)&Bs[k][tx * 4];
            float af[4] = {a.x, a.y, a.z, a.w};
            float bf[4] = {b.x, b.y, b.z, b.w};
#pragma unroll
            for (int i = 0; i < 4; i++)
#pragma unroll
                for (int j = 0; j < 4; j++)
                    acc[i][j] = fmaf(af[i], bf[j], acc[i][j]);
        }
    }

    // Epilogue: bias + rotary + transposed store.
    // Columns owned: col0 + tx*4 + {0..3}; even base -> pairs (0,1),(2,3).
    const int cbase = col0 + tx * 4;
    const float b0 = bias[cbase + 0], b1 = bias[cbase + 1];
    const float b2 = bias[cbase + 2], b3 = bias[cbase + 3];
    const int o = cbase >> 6;            // head index (BN=64 aligned -> same o for all 4)
    const int hbase = cbase & 63;

#pragma unroll
    for (int i = 0; i < 4; i++) {
        const int mg = row0 + ty * 4 + i;
        const int bidx = mg >> 11;
        const int spos = mg & 2047;
        float v[4] = {acc[i][0] + b0, acc[i][1] + b1, acc[i][2] + b2, acc[i][3] + b3};
        float outv[4];
#pragma unroll
        for (int p = 0; p < 2; p++) {
            const int he = hbase + 2 * p;        // even h
            const float xe = v[2 * p], xo = v[2 * p + 1];
            float se, ce, so, co;
            sincosf((float)spos * inv_sh[he & 31], &se, &ce);
            sincosf((float)spos * inv_sh[(he + 1) & 31], &so, &co);
            outv[2 * p]     = xe * ce - xo * se;
            outv[2 * p + 1] = xo * co + xe * so;
        }
        float* d = dst + (((size_t)(bidx * NHEAD + o) * SEQ + spos) * HDIM + hbase);
        float4 st = make_float4(outv[0] * scale, outv[1] * scale,
                                outv[2] * scale, outv[3] * scale);
        *(float4*)d = st;
    }
}

// ---------------------------------------------------------------------------
// Kernel 2: per (b,o): logits[m][n] = SR[m,:] . ER[n,:]  (K=64), fused masks.
// Tile 64x64, 256 threads, 4x4 micro-tile, full K in smem.
// ---------------------------------------------------------------------------
__global__ __launch_bounds__(256) void logits_kernel(
    const float* __restrict__ mask, float* __restrict__ out)
{
    const int z = blockIdx.z;          // b*8 + o
    const int b = z >> 3;
    const float* __restrict__ A = g_SR + (size_t)z * SEQ * HDIM;
    const float* __restrict__ Bm = g_ER + (size_t)z * SEQ * HDIM;

    const int m0 = blockIdx.y * 64;
    const int n0 = blockIdx.x * 64;

    __shared__ float As[64][68];   // [k][m]
    __shared__ float Bs[64][68];   // [k][n]

    const int tid = threadIdx.x;
    const int tx = tid & 15;
    const int ty = tid >> 4;

    const int lrow = tid >> 4;         // 0..15
    const int lk   = (tid & 15) * 4;   // 0..60

#pragma unroll
    for (int j = 0; j < 4; j++) {
        const int r = lrow + j * 16;
        float4 av = *(const float4*)&A[(size_t)(m0 + r) * HDIM + lk];
        As[lk + 0][r] = av.x; As[lk + 1][r] = av.y;
        As[lk + 2][r] = av.z; As[lk + 3][r] = av.w;
        float4 bv = *(const float4*)&Bm[(size_t)(n0 + r) * HDIM + lk];
        Bs[lk + 0][r] = bv.x; Bs[lk + 1][r] = bv.y;
        Bs[lk + 2][r] = bv.z; Bs[lk + 3][r] = bv.w;
    }
    __syncthreads();

    float acc[4][4];
#pragma unroll
    for (int i = 0; i < 4; i++)
#pragma unroll
        for (int j = 0; j < 4; j++) acc[i][j] = 0.0f;

#pragma unroll 16
    for (int k = 0; k < 64; k++) {
        float4 a = *(const float4*)&As[k][ty * 4];
        float4 b = *(const float4*)&Bs[k][tx * 4];
        float af[4] = {a.x, a.y, a.z, a.w};
        float bf[4] = {b.x, b.y, b.z, b.w};
#pragma unroll
        for (int i = 0; i < 4; i++)
#pragma unroll
            for (int j = 0; j < 4; j++)
                acc[i][j] = fmaf(af[i], bf[j], acc[i][j]);
    }

    // Epilogue: pad mask (on n / key axis) + strict-lower-triangular -NEG.
    const int nb = n0 + tx * 4;
    const float4 pv = *(const float4*)&mask[b * SEQ + nb];
    const float pad[4] = {pv.x, pv.y, pv.z, pv.w};

#pragma unroll
    for (int i = 0; i < 4; i++) {
        const int m = m0 + ty * 4 + i;
        float v[4];
#pragma unroll
        for (int j = 0; j < 4; j++) {
            const int n = nb + j;
            float x = acc[i][j];                       // 1/8 already folded into SR
            x = x * pad[j] - (1.0f - pad[j]) * NEGV;   // pad mask
            if (n < m) x -= NEGV;                      // strict lower triangle
            v[j] = x;
        }
        float* d = out + (((size_t)z * SEQ + m) * SEQ + nb);
        *(float4*)d = make_float4(v[0], v[1], v[2], v[3]);
    }
}

extern "C" void kernel_launch(void* const* d_in, const int* in_sizes, int n_in,
                              void* d_out, int out_size)
{
    const float* X    = (const float*)d_in[0];
    const float* mask = (const float*)d_in[1];
    const float* Ws   = (const float*)d_in[2];
    const float* bs   = (const float*)d_in[3];
    const float* We   = (const float*)d_in[4];
    const float* be   = (const float*)d_in[5];
    float* out = (float*)d_out;

    dim3 g1(NHEAD * HDIM / 64, (BATCH * SEQ) / 64, 2);   // (8, 64, 2)
    proj_rope_kernel<<<g1, 256>>>(X, Ws, bs, We, be);

    dim3 g2(SEQ / 64, SEQ / 64, BATCH * NHEAD);          // (32, 32, 16)
    logits_kernel<<<g2, 256>>>(mask, out);
}

// round 3
// speedup vs baseline: 1.9425x; 1.9425x over previous
#include <cuda_runtime.h>
#include <cuda_bf16.h>
#include <math.h>

#define SEQ 2048
#define BATCH 2
#define DIN 768
#define NHEAD 8
#define HDIM 64
#define NEGV 1000000000000.0f

// Scratch: rotated start/end projections in bf16, layout [b][o][s][h] (k-contiguous)
__device__ __nv_bfloat16 g_SR[BATCH * NHEAD * SEQ * HDIM];
__device__ __nv_bfloat16 g_ER[BATCH * NHEAD * SEQ * HDIM];

// ---------------------------------------------------------------------------
// Kernel 1: projection GEMM (M=4096, N=512, K=768) + bias + interleaved rotary
// blockIdx.z = 0 -> Ws/bs -> g_SR (scaled by 1/8), z = 1 -> We/be -> g_ER
// Tile: BM=64, BN=64, BK=16, 256 threads, 4x4 micro-tile. fp32 FFMA.
// ---------------------------------------------------------------------------
__global__ __launch_bounds__(256) void proj_rope_kernel(
    const float* __restrict__ X,
    const float* __restrict__ Ws, const float* __restrict__ bs,
    const float* __restrict__ We, const float* __restrict__ be)
{
    const int which = blockIdx.z;
    const float* __restrict__ W = which ? We : Ws;
    const float* __restrict__ bias = which ? be : bs;
    __nv_bfloat16* __restrict__ dst = which ? g_ER : g_SR;
    const float scale = which ? 1.0f : 0.125f;  // 1/sqrt(64) folded into start

    __shared__ float As[16][68];   // [k][m]
    __shared__ float Bs[16][64];   // [k][n]
    __shared__ float inv_sh[32];

    const int tid = threadIdx.x;
    const int tx = tid & 15;
    const int ty = tid >> 4;

    if (tid < 32) {
        inv_sh[tid] = (float)exp(-(double)tid * 9.210340371976184 / 32.0);
    }

    const int row0 = blockIdx.y * 64;
    const int col0 = blockIdx.x * 64;

    const int aRow = tid >> 2;
    const int aK   = (tid & 3) * 4;
    const int bK   = tid >> 4;
    const int bN   = (tid & 15) * 4;

    float acc[4][4];
#pragma unroll
    for (int i = 0; i < 4; i++)
#pragma unroll
        for (int j = 0; j < 4; j++) acc[i][j] = 0.0f;

    for (int k0 = 0; k0 < DIN; k0 += 16) {
        __syncthreads();
        float4 av = *(const float4*)&X[(size_t)(row0 + aRow) * DIN + k0 + aK];
        As[aK + 0][aRow] = av.x;
        As[aK + 1][aRow] = av.y;
        As[aK + 2][aRow] = av.z;
        As[aK + 3][aRow] = av.w;
        *(float4*)&Bs[bK][bN] = *(const float4*)&W[(size_t)(k0 + bK) * (NHEAD * HDIM) + col0 + bN];
        __syncthreads();

#pragma unroll
        for (int k = 0; k < 16; k++) {
            float4 a = *(const float4*)&As[k][ty * 4];
            float4 b = *(const float4*)&Bs[k][tx * 4];
            float af[4] = {a.x, a.y, a.z, a.w};
            float bf[4] = {b.x, b.y, b.z, b.w};
#pragma unroll
            for (int i = 0; i < 4; i++)
#pragma unroll
                for (int j = 0; j < 4; j++)
                    acc[i][j] = fmaf(af[i], bf[j], acc[i][j]);
        }
    }

    // Epilogue: bias + rotary + bf16 store to [b][o][s][h]
    const int cbase = col0 + tx * 4;
    const float b0 = bias[cbase + 0], b1 = bias[cbase + 1];
    const float b2 = bias[cbase + 2], b3 = bias[cbase + 3];
    const int o = cbase >> 6;
    const int hbase = cbase & 63;

#pragma unroll
    for (int i = 0; i < 4; i++) {
        const int mg = row0 + ty * 4 + i;
        const int bidx = mg >> 11;
        const int spos = mg & 2047;
        float v[4] = {acc[i][0] + b0, acc[i][1] + b1, acc[i][2] + b2, acc[i][3] + b3};
        float outv[4];
#pragma unroll
        for (int p = 0; p < 2; p++) {
            const int he = hbase + 2 * p;
            const float xe = v[2 * p], xo = v[2 * p + 1];
            float se, ce, so, co;
            sincosf((float)spos * inv_sh[he & 31], &se, &ce);
            sincosf((float)spos * inv_sh[(he + 1) & 31], &so, &co);
            outv[2 * p]     = xe * ce - xo * se;
            outv[2 * p + 1] = xo * co + xe * so;
        }
        __nv_bfloat16* d = dst + (((size_t)(bidx * NHEAD + o) * SEQ + spos) * HDIM + hbase);
        __nv_bfloat162 p0, p1;
        p0.x = __float2bfloat16(outv[0] * scale);
        p0.y = __float2bfloat16(outv[1] * scale);
        p1.x = __float2bfloat16(outv[2] * scale);
        p1.y = __float2bfloat16(outv[3] * scale);
        uint2 st;
        st.x = *(unsigned int*)&p0;
        st.y = *(unsigned int*)&p1;
        *(uint2*)d = st;
    }
}

// ---------------------------------------------------------------------------
// Kernel 2: per (b,o): logits[m][n] = SR[m,:] . ER[n,:]  (K=64), bf16 HMMA.
// CTA tile 128x128, 8 warps (2 M x 4 N), warp tile 64x32, whole K in smem.
// ---------------------------------------------------------------------------
__device__ __forceinline__ unsigned smem_u32(const void* p) {
    return (unsigned)__cvta_generic_to_shared(p);
}

__device__ __forceinline__ void ldm_x4(unsigned addr, unsigned& r0, unsigned& r1,
                                       unsigned& r2, unsigned& r3) {
    asm volatile("ldmatrix.sync.aligned.m8n8.x4.shared.b16 {%0,%1,%2,%3}, [%4];"
                 : "=r"(r0), "=r"(r1), "=r"(r2), "=r"(r3) : "r"(addr));
}

__device__ __forceinline__ void mma_bf16(float c[4], unsigned a0, unsigned a1,
                                         unsigned a2, unsigned a3,
                                         unsigned b0, unsigned b1) {
    asm volatile("mma.sync.aligned.m16n8k16.row.col.f32.bf16.bf16.f32 "
                 "{%0,%1,%2,%3}, {%4,%5,%6,%7}, {%8,%9}, {%0,%1,%2,%3};"
                 : "+f"(c[0]), "+f"(c[1]), "+f"(c[2]), "+f"(c[3])
                 : "r"(a0), "r"(a1), "r"(a2), "r"(a3), "r"(b0), "r"(b1));
}

#define SWZ(off) ((off) ^ (((off) >> 3) & 0x70))

__global__ __launch_bounds__(256) void logits_kernel(
    const float* __restrict__ mask, float* __restrict__ out)
{
    const int z = blockIdx.z;          // b*8 + o
    const int b = z >> 3;
    const char* __restrict__ Ag = (const char*)(g_SR + (size_t)z * SEQ * HDIM);
    const char* __restrict__ Bg = (const char*)(g_ER + (size_t)z * SEQ * HDIM);

    const int m0 = blockIdx.y * 128;
    const int n0 = blockIdx.x * 128;

    __shared__ __align__(1024) char sA[128 * 128];   // 128 rows x 64 bf16 (128B/row), SW128
    __shared__ __align__(1024) char sB[128 * 128];

    const int tid = threadIdx.x;

    // Load A and B tiles: 1024 x 16B chunks each, swizzled
#pragma unroll
    for (int i = 0; i < 4; i++) {
        const int c = tid + i * 256;           // 0..1023
        const int row = c >> 3;
        const int cb = (c & 7) * 16;
        const unsigned off = row * 128 + cb;
        const unsigned sw = SWZ(off);
        *(uint4*)(sA + sw) = *(const uint4*)(Ag + (size_t)(m0 + row) * 128 + cb);
        *(uint4*)(sB + sw) = *(const uint4*)(Bg + (size_t)(n0 + row) * 128 + cb);
    }
    __syncthreads();

    const int wid = tid >> 5;
    const int lane = tid & 31;
    const int wm = (wid & 1) * 64;     // warp M offset in tile
    const int wn = (wid >> 1) * 32;    // warp N offset in tile

    const unsigned sAb = smem_u32(sA);
    const unsigned sBb = smem_u32(sB);

    float acc[4][4][4];
#pragma unroll
    for (int mf = 0; mf < 4; mf++)
#pragma unroll
        for (int nf = 0; nf < 4; nf++)
#pragma unroll
            for (int r = 0; r < 4; r++) acc[mf][nf][r] = 0.0f;

    // lane-dependent parts of ldmatrix addresses
    const int aRowL = (lane & 7) + ((lane >> 3) & 1) * 8;   // 0..15
    const int aColB = (lane >> 4) * 16;                     // 0 or 16 bytes
    const int bRowL = (lane & 7) + (lane >> 4) * 8;         // 0..15
    const int bColB = ((lane >> 3) & 1) * 16;               // 0 or 16 bytes

#pragma unroll
    for (int k = 0; k < 4; k++) {
        const int kb = k * 32;   // byte offset of k-step
        unsigned a[4][4];
#pragma unroll
        for (int mf = 0; mf < 4; mf++) {
            const unsigned off = (unsigned)((wm + mf * 16 + aRowL) * 128 + kb + aColB);
            ldm_x4(sAb + SWZ(off), a[mf][0], a[mf][1], a[mf][2], a[mf][3]);
        }
        unsigned bb[8];
#pragma unroll
        for (int np = 0; np < 2; np++) {
            const unsigned off = (unsigned)((wn + np * 16 + bRowL) * 128 + kb + bColB);
            ldm_x4(sBb + SWZ(off), bb[np * 4 + 0], bb[np * 4 + 1],
                   bb[np * 4 + 2], bb[np * 4 + 3]);
        }
#pragma unroll
        for (int mf = 0; mf < 4; mf++) {
#pragma unroll
            for (int nf = 0; nf < 4; nf++) {
                const int np = nf >> 1;
                const int sub = nf & 1;   // 0 -> regs {0,1}, 1 -> regs {2,3}
                mma_bf16(acc[mf][nf], a[mf][0], a[mf][1], a[mf][2], a[mf][3],
                         bb[np * 4 + sub * 2], bb[np * 4 + sub * 2 + 1]);
            }
        }
    }

    // Epilogue: pad mask (n axis) + strict lower triangle, float2 stores.
    const int q = lane >> 2;            // row group 0..7
    const int nlo = (lane & 3) * 2;     // col pair base within 8

    float2 pv[4];
#pragma unroll
    for (int nf = 0; nf < 4; nf++) {
        const int n = n0 + wn + nf * 8 + nlo;
        pv[nf] = *(const float2*)&mask[b * SEQ + n];
    }

#pragma unroll
    for (int mf = 0; mf < 4; mf++) {
#pragma unroll
        for (int half = 0; half < 2; half++) {
            const int m = m0 + wm + mf * 16 + q + half * 8;
            float* rowp = out + ((size_t)z * SEQ + m) * SEQ;
#pragma unroll
            for (int nf = 0; nf < 4; nf++) {
                const int n = n0 + wn + nf * 8 + nlo;
                float x0 = acc[mf][nf][half * 2 + 0];
                float x1 = acc[mf][nf][half * 2 + 1];
                const float p0 = pv[nf].x, p1 = pv[nf].y;
                x0 = x0 * p0 - (1.0f - p0) * NEGV;
                x1 = x1 * p1 - (1.0f - p1) * NEGV;
                if (n < m)     x0 -= NEGV;
                if (n + 1 < m) x1 -= NEGV;
                *(float2*)(rowp + n) = make_float2(x0, x1);
            }
        }
    }
}

extern "C" void kernel_launch(void* const* d_in, const int* in_sizes, int n_in,
                              void* d_out, int out_size)
{
    const float* X    = (const float*)d_in[0];
    const float* mask = (const float*)d_in[1];
    const float* Ws   = (const float*)d_in[2];
    const float* bs   = (const float*)d_in[3];
    const float* We   = (const float*)d_in[4];
    const float* be   = (const float*)d_in[5];
    float* out = (float*)d_out;

    dim3 g1(NHEAD * HDIM / 64, (BATCH * SEQ) / 64, 2);   // (8, 64, 2)
    proj_rope_kernel<<<g1, 256>>>(X, Ws, bs, We, be);

    dim3 g2(SEQ / 128, SEQ / 128, BATCH * NHEAD);        // (16, 16, 16)
    logits_kernel<<<g2, 256>>>(mask, out);
}

// round 7
// speedup vs baseline: 4.3561x; 2.2426x over previous
#include <cuda_runtime.h>
#include <cuda_bf16.h>
#include <math.h>

#define SEQ 2048
#define BATCH 2
#define DIN 768
#define NHEAD 8
#define HDIM 64
#define NPROJ 1024          // 512 start + 512 end, fused
#define NEGV 1000000000000.0f

// Scratch
__device__ __nv_bfloat16 g_SR[BATCH * NHEAD * SEQ * HDIM];
__device__ __nv_bfloat16 g_ER[BATCH * NHEAD * SEQ * HDIM];
__device__ __nv_bfloat16 g_Xb[BATCH * SEQ * DIN];        // X in bf16
__device__ __nv_bfloat16 g_Wt[NPROJ * DIN];              // W^T (n-major, k-contiguous)
__device__ float2        g_tab[SEQ * 32];                // (sin, cos) per (pos, freq)

// ---------------------------------------------------------------------------
// Prep kernels
// ---------------------------------------------------------------------------
__global__ __launch_bounds__(256) void convert_x_kernel(const float* __restrict__ X)
{
    const int idx = blockIdx.x * 256 + threadIdx.x;    // 786432 float4s
    float4 v = ((const float4*)X)[idx];
    __nv_bfloat162 p0, p1;
    p0.x = __float2bfloat16(v.x); p0.y = __float2bfloat16(v.y);
    p1.x = __float2bfloat16(v.z); p1.y = __float2bfloat16(v.w);
    uint2 st; st.x = *(unsigned*)&p0; st.y = *(unsigned*)&p1;
    ((uint2*)g_Xb)[idx] = st;
}

__global__ __launch_bounds__(256) void transpose_w_kernel(
    const float* __restrict__ Ws, const float* __restrict__ We)
{
    // block (32,8): tile 32(k) x 32(n).  grid (24, 32)
    __shared__ float t[32][33];
    const int k0 = blockIdx.x * 32;
    const int n0 = blockIdx.y * 32;
    const int tx = threadIdx.x, ty = threadIdx.y;
    const int nn = n0 + tx;
    const float* __restrict__ src = (nn < 512) ? Ws : We;
    const int ncol = nn & 511;
#pragma unroll
    for (int j = 0; j < 32; j += 8)
        t[ty + j][tx] = src[(size_t)(k0 + ty + j) * 512 + ncol];
    __syncthreads();
#pragma unroll
    for (int j = 0; j < 32; j += 8) {
        const int n = n0 + ty + j;
        g_Wt[(size_t)n * DIN + k0 + tx] = __float2bfloat16(t[tx][ty + j]);
    }
}

__global__ __launch_bounds__(256) void rope_table_kernel()
{
    const int idx = blockIdx.x * 256 + threadIdx.x;    // 65536
    const int spos = idx >> 5;
    const int i = idx & 31;
    const float inv = (float)exp(-(double)i * 9.210340371976184 / 32.0);
    float s, c;
    sincosf((float)spos * inv, &s, &c);
    g_tab[idx] = make_float2(s, c);
}

// ---------------------------------------------------------------------------
// Shared HMMA helpers
// ---------------------------------------------------------------------------
__device__ __forceinline__ unsigned smem_u32(const void* p) {
    return (unsigned)__cvta_generic_to_shared(p);
}
__device__ __forceinline__ void ldm_x4(unsigned addr, unsigned& r0, unsigned& r1,
                                       unsigned& r2, unsigned& r3) {
    asm volatile("ldmatrix.sync.aligned.m8n8.x4.shared.b16 {%0,%1,%2,%3}, [%4];"
                 : "=r"(r0), "=r"(r1), "=r"(r2), "=r"(r3) : "r"(addr));
}
__device__ __forceinline__ void mma_bf16(float c[4], unsigned a0, unsigned a1,
                                         unsigned a2, unsigned a3,
                                         unsigned b0, unsigned b1) {
    asm volatile("mma.sync.aligned.m16n8k16.row.col.f32.bf16.bf16.f32 "
                 "{%0,%1,%2,%3}, {%4,%5,%6,%7}, {%8,%9}, {%0,%1,%2,%3};"
                 : "+f"(c[0]), "+f"(c[1]), "+f"(c[2]), "+f"(c[3])
                 : "r"(a0), "r"(a1), "r"(a2), "r"(a3), "r"(b0), "r"(b1));
}
__device__ __forceinline__ void cp_async16(unsigned saddr, const void* gptr) {
    asm volatile("cp.async.cg.shared.global [%0], [%1], 16;" :: "r"(saddr), "l"(gptr));
}
#define CP_COMMIT() asm volatile("cp.async.commit_group;")
#define CP_WAIT(n)  asm volatile("cp.async.wait_group %0;" :: "n"(n))
#define SWZ(off) ((off) ^ (((off) >> 3) & 0x70))

// ---------------------------------------------------------------------------
// Projection GEMM: C[4096][1024] = Xb @ Wt^T, bf16 HMMA, fused bias+rope.
// CTA 128x128, BK=64, double-buffered cp.async. 8 warps (2M x 4N), warp 64x32.
// ---------------------------------------------------------------------------
__global__ __launch_bounds__(256) void proj_mma_kernel(
    const float* __restrict__ bs, const float* __restrict__ be)
{
    extern __shared__ __align__(1024) char smem[];
    char* bufA[2] = { smem,          smem + 32768 };
    char* bufB[2] = { smem + 16384,  smem + 49152 };

    const int n0 = blockIdx.x * 128;
    const int m0 = blockIdx.y * 128;
    const int tid = threadIdx.x;

    // per-thread load slots: 4 chunks of 16B for A and for B per stage
    const int lrow[4] = { (tid + 0) >> 3, (tid + 256) >> 3, (tid + 512) >> 3, (tid + 768) >> 3 };
    const int lcb = (tid & 7) * 16;

    const char* Agbase = (const char*)g_Xb + (size_t)m0 * (DIN * 2) + lcb;
    const char* Bgbase = (const char*)g_Wt + (size_t)n0 * (DIN * 2) + lcb;

    // prologue: stage 0
    {
#pragma unroll
        for (int i = 0; i < 4; i++) {
            const unsigned sw = SWZ((unsigned)(lrow[i] * 128 + lcb));
            cp_async16(smem_u32(bufA[0]) + sw, Agbase + (size_t)lrow[i] * (DIN * 2));
            cp_async16(smem_u32(bufB[0]) + sw, Bgbase + (size_t)lrow[i] * (DIN * 2));
        }
        CP_COMMIT();
    }

    const int wid = tid >> 5;
    const int lane = tid & 31;
    const int wm = (wid & 1) * 64;
    const int wn = (wid >> 1) * 32;

    const int aRowL = (lane & 7) + ((lane >> 3) & 1) * 8;
    const int aColB = (lane >> 4) * 16;
    const int bRowL = (lane & 7) + (lane >> 4) * 8;
    const int bColB = ((lane >> 3) & 1) * 16;

    float acc[4][4][4];
#pragma unroll
    for (int mf = 0; mf < 4; mf++)
#pragma unroll
        for (int nf = 0; nf < 4; nf++)
#pragma unroll
            for (int r = 0; r < 4; r++) acc[mf][nf][r] = 0.0f;

    for (int ks = 0; ks < DIN / 64; ks++) {
        if (ks + 1 < DIN / 64) {
            const int nb = (ks + 1) & 1;
            const size_t koff = (size_t)(ks + 1) * 128;   // 64 bf16 = 128 bytes
#pragma unroll
            for (int i = 0; i < 4; i++) {
                const unsigned sw = SWZ((unsigned)(lrow[i] * 128 + lcb));
                cp_async16(smem_u32(bufA[nb]) + sw, Agbase + (size_t)lrow[i] * (DIN * 2) + koff);
                cp_async16(smem_u32(bufB[nb]) + sw, Bgbase + (size_t)lrow[i] * (DIN * 2) + koff);
            }
            CP_COMMIT();
            CP_WAIT(1);
        } else {
            CP_WAIT(0);
        }
        __syncthreads();

        const unsigned sAb = smem_u32(bufA[ks & 1]);
        const unsigned sBb = smem_u32(bufB[ks & 1]);
#pragma unroll
        for (int k = 0; k < 4; k++) {
            const int kb = k * 32;
            unsigned a[4][4];
#pragma unroll
            for (int mf = 0; mf < 4; mf++) {
                const unsigned off = (unsigned)((wm + mf * 16 + aRowL) * 128 + kb + aColB);
                ldm_x4(sAb + SWZ(off), a[mf][0], a[mf][1], a[mf][2], a[mf][3]);
            }
            unsigned bb[8];
#pragma unroll
            for (int np = 0; np < 2; np++) {
                const unsigned off = (unsigned)((wn + np * 16 + bRowL) * 128 + kb + bColB);
                ldm_x4(sBb + SWZ(off), bb[np * 4 + 0], bb[np * 4 + 1],
                       bb[np * 4 + 2], bb[np * 4 + 3]);
            }
#pragma unroll
            for (int mf = 0; mf < 4; mf++)
#pragma unroll
                for (int nf = 0; nf < 4; nf++) {
                    const int np = nf >> 1, sub = nf & 1;
                    mma_bf16(acc[mf][nf], a[mf][0], a[mf][1], a[mf][2], a[mf][3],
                             bb[np * 4 + sub * 2], bb[np * 4 + sub * 2 + 1]);
                }
        }
        __syncthreads();
    }

    // Epilogue: bias + rope + bf16 store. Each thread holds even/odd col pairs.
    const int q = lane >> 2;
    const int nlo = (lane & 3) * 2;

#pragma unroll
    for (int nf = 0; nf < 4; nf++) {
        const int n = n0 + wn + nf * 8 + nlo;        // even
        const int which = n >> 9;
        const int nc = n & 511;
        const int o = nc >> 6;
        const int h = n & 63;
        const int f0 = h & 31;                        // even
        const float* bp = which ? be : bs;
        const float b0 = bp[nc], b1 = bp[nc + 1];
        const float scale = which ? 1.0f : 0.125f;
        __nv_bfloat16* dstb = which ? g_ER : g_SR;
#pragma unroll
        for (int mf = 0; mf < 4; mf++)
#pragma unroll
            for (int half = 0; half < 2; half++) {
                const int m = m0 + wm + mf * 16 + q + half * 8;
                const int bidx = m >> 11;
                const int spos = m & 2047;
                const float4 sc = *(const float4*)&g_tab[spos * 32 + f0]; // s_e,c_e,s_o,c_o
                const float v0 = acc[mf][nf][half * 2 + 0] + b0;
                const float v1 = acc[mf][nf][half * 2 + 1] + b1;
                const float r0 = (v0 * sc.y - v1 * sc.x) * scale;
                const float r1 = (v1 * sc.w + v0 * sc.z) * scale;
                __nv_bfloat162 p;
                p.x = __float2bfloat16(r0);
                p.y = __float2bfloat16(r1);
                *(unsigned*)&dstb[(((size_t)(bidx * NHEAD + o)) * SEQ + spos) * HDIM + h]
                    = *(unsigned*)&p;
            }
    }
}

// ---------------------------------------------------------------------------
// Kernel 2: per (b,o): logits[m][n] = SR[m,:] . ER[n,:]  (K=64), bf16 HMMA.
// (unchanged from round 2)
// ---------------------------------------------------------------------------
__global__ __launch_bounds__(256) void logits_kernel(
    const float* __restrict__ mask, float* __restrict__ out)
{
    const int z = blockIdx.z;
    const int b = z >> 3;
    const char* __restrict__ Ag = (const char*)(g_SR + (size_t)z * SEQ * HDIM);
    const char* __restrict__ Bg = (const char*)(g_ER + (size_t)z * SEQ * HDIM);

    const int m0 = blockIdx.y * 128;
    const int n0 = blockIdx.x * 128;

    __shared__ __align__(1024) char sA[128 * 128];
    __shared__ __align__(1024) char sB[128 * 128];

    const int tid = threadIdx.x;

#pragma unroll
    for (int i = 0; i < 4; i++) {
        const int c = tid + i * 256;
        const int row = c >> 3;
        const int cb = (c & 7) * 16;
        const unsigned sw = SWZ((unsigned)(row * 128 + cb));
        *(uint4*)(sA + sw) = *(const uint4*)(Ag + (size_t)(m0 + row) * 128 + cb);
        *(uint4*)(sB + sw) = *(const uint4*)(Bg + (size_t)(n0 + row) * 128 + cb);
    }
    __syncthreads();

    const int wid = tid >> 5;
    const int lane = tid & 31;
    const int wm = (wid & 1) * 64;
    const int wn = (wid >> 1) * 32;

    const unsigned sAb = smem_u32(sA);
    const unsigned sBb = smem_u32(sB);

    float acc[4][4][4];
#pragma unroll
    for (int mf = 0; mf < 4; mf++)
#pragma unroll
        for (int nf = 0; nf < 4; nf++)
#pragma unroll
            for (int r = 0; r < 4; r++) acc[mf][nf][r] = 0.0f;

    const int aRowL = (lane & 7) + ((lane >> 3) & 1) * 8;
    const int aColB = (lane >> 4) * 16;
    const int bRowL = (lane & 7) + (lane >> 4) * 8;
    const int bColB = ((lane >> 3) & 1) * 16;

#pragma unroll
    for (int k = 0; k < 4; k++) {
        const int kb = k * 32;
        unsigned a[4][4];
#pragma unroll
        for (int mf = 0; mf < 4; mf++) {
            const unsigned off = (unsigned)((wm + mf * 16 + aRowL) * 128 + kb + aColB);
            ldm_x4(sAb + SWZ(off), a[mf][0], a[mf][1], a[mf][2], a[mf][3]);
        }
        unsigned bb[8];
#pragma unroll
        for (int np = 0; np < 2; np++) {
            const unsigned off = (unsigned)((wn + np * 16 + bRowL) * 128 + kb + bColB);
            ldm_x4(sBb + SWZ(off), bb[np * 4 + 0], bb[np * 4 + 1],
                   bb[np * 4 + 2], bb[np * 4 + 3]);
        }
#pragma unroll
        for (int mf = 0; mf < 4; mf++) {
#pragma unroll
            for (int nf = 0; nf < 4; nf++) {
                const int np = nf >> 1;
                const int sub = nf & 1;
                mma_bf16(acc[mf][nf], a[mf][0], a[mf][1], a[mf][2], a[mf][3],
                         bb[np * 4 + sub * 2], bb[np * 4 + sub * 2 + 1]);
            }
        }
    }

    const int q = lane >> 2;
    const int nlo = (lane & 3) * 2;

    float2 pv[4];
#pragma unroll
    for (int nf = 0; nf < 4; nf++) {
        const int n = n0 + wn + nf * 8 + nlo;
        pv[nf] = *(const float2*)&mask[b * SEQ + n];
    }

#pragma unroll
    for (int mf = 0; mf < 4; mf++) {
#pragma unroll
        for (int half = 0; half < 2; half++) {
            const int m = m0 + wm + mf * 16 + q + half * 8;
            float* rowp = out + ((size_t)z * SEQ + m) * SEQ;
#pragma unroll
            for (int nf = 0; nf < 4; nf++) {
                const int n = n0 + wn + nf * 8 + nlo;
                float x0 = acc[mf][nf][half * 2 + 0];
                float x1 = acc[mf][nf][half * 2 + 1];
                const float p0 = pv[nf].x, p1 = pv[nf].y;
                x0 = x0 * p0 - (1.0f - p0) * NEGV;
                x1 = x1 * p1 - (1.0f - p1) * NEGV;
                if (n < m)     x0 -= NEGV;
                if (n + 1 < m) x1 -= NEGV;
                *(float2*)(rowp + n) = make_float2(x0, x1);
            }
        }
    }
}

extern "C" void kernel_launch(void* const* d_in, const int* in_sizes, int n_in,
                              void* d_out, int out_size)
{
    const float* X    = (const float*)d_in[0];
    const float* mask = (const float*)d_in[1];
    const float* Ws   = (const float*)d_in[2];
    const float* bs   = (const float*)d_in[3];
    const float* We   = (const float*)d_in[4];
    const float* be   = (const float*)d_in[5];
    float* out = (float*)d_out;

    cudaFuncSetAttribute(proj_mma_kernel,
                         cudaFuncAttributeMaxDynamicSharedMemorySize, 65536);

    convert_x_kernel<<<BATCH * SEQ * DIN / 1024, 256>>>(X);
    transpose_w_kernel<<<dim3(DIN / 32, NPROJ / 32), dim3(32, 8)>>>(Ws, We);
    rope_table_kernel<<<SEQ * 32 / 256, 256>>>();

    dim3 g1(NPROJ / 128, BATCH * SEQ / 128);             // (8, 32)
    proj_mma_kernel<<<g1, 256, 65536>>>(bs, be);

    dim3 g2(SEQ / 128, SEQ / 128, BATCH * NHEAD);        // (16, 16, 16)
    logits_kernel<<<g2, 256>>>(mask, out);
}